// round 2
// baseline (speedup 1.0000x reference)
#include <cuda_runtime.h>
#include <cstdint>

// Problem dims
#define B_ 16
#define L_ 512
#define H_ 8
#define E_ 64
#define BH_ (B_ * H_)          // 128
#define SCALE 0.125f           // 1/sqrt(64)

// ---------- f32x2 packed helpers (FFMA2 path; rt doubles fp32 throughput) ----------
__device__ __forceinline__ unsigned long long dup2(float a) {
    unsigned long long r;
    asm("mov.b64 %0, {%1, %1};" : "=l"(r) : "f"(a));
    return r;
}
__device__ __forceinline__ void fma2(unsigned long long& d,
                                     unsigned long long a,
                                     unsigned long long b) {
    asm("fma.rn.f32x2 %0, %1, %2, %0;" : "+l"(d) : "l"(a), "l"(b));
}
__device__ __forceinline__ float2 unpk(unsigned long long v) {
    float2 f;
    asm("mov.b64 {%0, %1}, %2;" : "=f"(f.x), "=f"(f.y) : "l"(v));
    return f;
}

// Accurate-enough exp immune to compiler fast-math flags:
// exp(x) = 2^(x*log2e), argument in hi/lo split (~1 ulp of t), ex2.approx (~2^-22 rel).
__device__ __forceinline__ float exp_acc(float x) {
    float m = __fmul_rn(x, 1.4426950408889634f);
    float t = __fmaf_rn(x, 1.925962991e-8f, m);   // log2(e) lo correction
    float r;
    asm("ex2.approx.ftz.f32 %0, %1;" : "=f"(r) : "f"(t));
    return r;
}

// ======================================================================
// Kernel 1: attn[bh, l, s] = SCALE * sum_e Q[b,l,h,e] * K[b,s,h,e]
// ======================================================================
__global__ void __launch_bounds__(256) gemm_qk_kernel(
    const float* __restrict__ q,
    const float* __restrict__ k,
    float* __restrict__ attn)
{
    __shared__ float AsT[32][132];   // [e within chunk][row i]
    __shared__ float BsT[32][132];

    const int bh = blockIdx.z;
    const int b  = bh >> 3;
    const int h  = bh & 7;
    const int it = blockIdx.y;       // l-tile (0..3)
    const int jt = blockIdx.x;       // s-tile (0..3)
    const int tid = threadIdx.x;
    const int tx = tid & 15;         // 16 col groups
    const int ty = tid >> 4;         // 16 row groups

    unsigned long long acc[8][4];
#pragma unroll
    for (int i = 0; i < 8; i++)
#pragma unroll
        for (int j = 0; j < 4; j++) acc[i][j] = 0ull;

    const float* qb = q + ((size_t)(b * L_) * H_ + h) * E_;
    const float* kb = k + ((size_t)(b * L_) * H_ + h) * E_;

#pragma unroll
    for (int ec = 0; ec < 2; ec++) {
#pragma unroll
        for (int r = 0; r < 4; r++) {
            int idx = tid + r * 256;
            int i   = idx >> 3;
            int e4  = idx & 7;
            int e   = ec * 32 + e4 * 4;
            float4 va = *(const float4*)(qb + (size_t)(it * 128 + i) * (H_ * E_) + e);
            AsT[e4 * 4 + 0][i] = va.x;
            AsT[e4 * 4 + 1][i] = va.y;
            AsT[e4 * 4 + 2][i] = va.z;
            AsT[e4 * 4 + 3][i] = va.w;
            float4 vb = *(const float4*)(kb + (size_t)(jt * 128 + i) * (H_ * E_) + e);
            BsT[e4 * 4 + 0][i] = vb.x;
            BsT[e4 * 4 + 1][i] = vb.y;
            BsT[e4 * 4 + 2][i] = vb.z;
            BsT[e4 * 4 + 3][i] = vb.w;
        }
        __syncthreads();

#pragma unroll
        for (int ee = 0; ee < 32; ee++) {
            float4 a0 = *(const float4*)&AsT[ee][ty * 4];
            float4 a1 = *(const float4*)&AsT[ee][64 + ty * 4];
            ulonglong2 b0 = *(const ulonglong2*)&BsT[ee][tx * 4];
            ulonglong2 b1 = *(const ulonglong2*)&BsT[ee][64 + tx * 4];

            unsigned long long ad[8];
            ad[0] = dup2(a0.x); ad[1] = dup2(a0.y);
            ad[2] = dup2(a0.z); ad[3] = dup2(a0.w);
            ad[4] = dup2(a1.x); ad[5] = dup2(a1.y);
            ad[6] = dup2(a1.z); ad[7] = dup2(a1.w);
            unsigned long long bp[4] = {b0.x, b0.y, b1.x, b1.y};

#pragma unroll
            for (int i = 0; i < 8; i++)
#pragma unroll
                for (int j = 0; j < 4; j++)
                    fma2(acc[i][j], ad[i], bp[j]);
        }
        __syncthreads();
    }

    float* outb = attn + ((size_t)bh * L_ + it * 128) * L_ + jt * 128;
#pragma unroll
    for (int ii = 0; ii < 8; ii++) {
        int row = (ii < 4) ? (ty * 4 + ii) : (64 + ty * 4 + ii - 4);
        float2 c0 = unpk(acc[ii][0]);
        float2 c1 = unpk(acc[ii][1]);
        float2 c2 = unpk(acc[ii][2]);
        float2 c3 = unpk(acc[ii][3]);
        float4 w0 = make_float4(c0.x * SCALE, c0.y * SCALE, c1.x * SCALE, c1.y * SCALE);
        float4 w1 = make_float4(c2.x * SCALE, c2.y * SCALE, c3.x * SCALE, c3.y * SCALE);
        *(float4*)(outb + (size_t)row * L_ + tx * 4) = w0;
        *(float4*)(outb + (size_t)row * L_ + 64 + tx * 4) = w1;
    }
}

// ======================================================================
// Kernel 2: per-row softmax (in-place) + prior + sigma_full.
// One warp per row. Precision-critical sigma path done in double on
// lane 0 (correctly-rounded 3^s), broadcast; element path mimics the
// reference's fp32 op sequence.
// ======================================================================
__global__ void __launch_bounds__(256) softmax_prior_kernel(
    float* __restrict__ series,
    const float* __restrict__ sigma,
    float* __restrict__ prior,
    float* __restrict__ sigf)
{
    const int w    = threadIdx.x >> 5;
    const int lane = threadIdx.x & 31;
    const int r    = blockIdx.x * 8 + w;     // row id 0..65535
    const int bh   = r >> 9;
    const int l    = r & 511;
    const int b    = bh >> 3;
    const int h    = bh & 7;

    float* row = series + (size_t)r * L_;
    float4 vv[4];
#pragma unroll
    for (int t = 0; t < 4; t++)
        vv[t] = *(const float4*)(row + t * 128 + lane * 4);

    float m = vv[0].x;
#pragma unroll
    for (int t = 0; t < 4; t++) {
        m = fmaxf(m, fmaxf(fmaxf(vv[t].x, vv[t].y), fmaxf(vv[t].z, vv[t].w)));
    }
#pragma unroll
    for (int o = 16; o > 0; o >>= 1)
        m = fmaxf(m, __shfl_xor_sync(0xffffffffu, m, o));

    float s = 0.f;
#pragma unroll
    for (int t = 0; t < 4; t++) {
        vv[t].x = exp_acc(vv[t].x - m); s += vv[t].x;
        vv[t].y = exp_acc(vv[t].y - m); s += vv[t].y;
        vv[t].z = exp_acc(vv[t].z - m); s += vv[t].z;
        vv[t].w = exp_acc(vv[t].w - m); s += vv[t].w;
    }
#pragma unroll
    for (int o = 16; o > 0; o >>= 1)
        s += __shfl_xor_sync(0xffffffffu, s, o);

    const float inv = __fdiv_rn(1.f, s);
#pragma unroll
    for (int t = 0; t < 4; t++) {
        vv[t].x *= inv; vv[t].y *= inv; vv[t].z *= inv; vv[t].w *= inv;
        *(float4*)(row + t * 128 + lane * 4) = vv[t];
    }

    // ---- sigma -> bandwidth (match reference fp32 rounding) ----
    // ref: s = sigmoid(5x)+1e-5 (fp32); sg = powf(3, s) - 1 (fp32).
    // Compute 3^s correctly rounded via double; subtraction is then exact.
    float sg;
    if (lane == 0) {
        double xd = (double)sigma[((size_t)b * L_ + l) * H_ + h];
        double sd = 1.0 / (1.0 + exp(-5.0 * xd));
        float sgm = (float)(sd + 1e-5);
        double P  = exp2((double)sgm * 1.5849625007211562);  // 3^sgm
        sg = (float)P - 1.0f;
    }
    sg = __shfl_sync(0xffffffffu, sg, 0);

    const float c    = __fdiv_rn(0.3989422804014327f, sg);     // 1/sqrt(2pi)/sig
    const float sg2  = __fmul_rn(sg, sg);
    const float den  = __fmul_rn(2.0f, sg2);                   // exact *2
    const float rinv = __fdiv_rn(1.0f, den);

    float* pr = prior + (size_t)r * L_;
    float* sf = sigf + (size_t)r * L_;
    const float4 sgv = make_float4(sg, sg, sg, sg);
#pragma unroll
    for (int t = 0; t < 4; t++) {
        int j0 = t * 128 + lane * 4;
        float d0 = (float)(l - j0);
        float d1 = (float)(l - (j0 + 1));
        float d2 = (float)(l - (j0 + 2));
        float d3 = (float)(l - (j0 + 3));
        float4 pv;
        pv.x = __fmul_rn(c, exp_acc(-__fmul_rn(__fmul_rn(d0, d0), rinv)));
        pv.y = __fmul_rn(c, exp_acc(-__fmul_rn(__fmul_rn(d1, d1), rinv)));
        pv.z = __fmul_rn(c, exp_acc(-__fmul_rn(__fmul_rn(d2, d2), rinv)));
        pv.w = __fmul_rn(c, exp_acc(-__fmul_rn(__fmul_rn(d3, d3), rinv)));
        *(float4*)(pr + j0) = pv;
        *(float4*)(sf + j0) = sgv;
    }
}

// ======================================================================
// Kernel 3: V[b,l,h,d] = sum_s P[bh,l,s] * values[b,s,h,d]
// ======================================================================
__global__ void __launch_bounds__(128) gemm_pv_kernel(
    const float* __restrict__ p,
    const float* __restrict__ v,
    float* __restrict__ out)
{
    __shared__ float PsT[32][132];
    __shared__ float Vs[32][68];

    const int bh = blockIdx.y;
    const int b  = bh >> 3;
    const int h  = bh & 7;
    const int mt = blockIdx.x;
    const int tid = threadIdx.x;
    const int tx = tid & 7;
    const int ty = tid >> 3;

    unsigned long long acc[8][4];
#pragma unroll
    for (int i = 0; i < 8; i++)
#pragma unroll
        for (int j = 0; j < 4; j++) acc[i][j] = 0ull;

    const float* prow = p + ((size_t)bh * L_ + mt * 128) * L_;
    const float* vb   = v + ((size_t)(b * L_) * H_ + h) * E_;

    for (int sc = 0; sc < 16; sc++) {
#pragma unroll
        for (int r = 0; r < 8; r++) {
            int idx = tid + r * 128;
            int i   = idx >> 3;
            int s4  = idx & 7;
            float4 vp = *(const float4*)(prow + (size_t)i * L_ + sc * 32 + s4 * 4);
            PsT[s4 * 4 + 0][i] = vp.x;
            PsT[s4 * 4 + 1][i] = vp.y;
            PsT[s4 * 4 + 2][i] = vp.z;
            PsT[s4 * 4 + 3][i] = vp.w;
        }
#pragma unroll
        for (int r = 0; r < 4; r++) {
            int idx = tid + r * 128;
            int s   = idx >> 4;
            int e4  = idx & 15;
            *(float4*)&Vs[s][e4 * 4] =
                *(const float4*)(vb + (size_t)(sc * 32 + s) * (H_ * E_) + e4 * 4);
        }
        __syncthreads();

#pragma unroll
        for (int ss = 0; ss < 32; ss++) {
            float4 p0 = *(const float4*)&PsT[ss][ty * 4];
            float4 p1 = *(const float4*)&PsT[ss][64 + ty * 4];
            ulonglong2 v0 = *(const ulonglong2*)&Vs[ss][tx * 4];
            ulonglong2 v1 = *(const ulonglong2*)&Vs[ss][32 + tx * 4];

            unsigned long long ad[8];
            ad[0] = dup2(p0.x); ad[1] = dup2(p0.y);
            ad[2] = dup2(p0.z); ad[3] = dup2(p0.w);
            ad[4] = dup2(p1.x); ad[5] = dup2(p1.y);
            ad[6] = dup2(p1.z); ad[7] = dup2(p1.w);
            unsigned long long bp[4] = {v0.x, v0.y, v1.x, v1.y};

#pragma unroll
            for (int i = 0; i < 8; i++)
#pragma unroll
                for (int j = 0; j < 4; j++)
                    fma2(acc[i][j], ad[i], bp[j]);
        }
        __syncthreads();
    }

#pragma unroll
    for (int ii = 0; ii < 8; ii++) {
        int row = (ii < 4) ? (ty * 4 + ii) : (64 + ty * 4 + ii - 4);
        int l = mt * 128 + row;
        float* ob = out + (((size_t)b * L_ + l) * H_ + h) * E_;
        float2 c0 = unpk(acc[ii][0]);
        float2 c1 = unpk(acc[ii][1]);
        float2 c2 = unpk(acc[ii][2]);
        float2 c3 = unpk(acc[ii][3]);
        *(float4*)(ob + tx * 4)      = make_float4(c0.x, c0.y, c1.x, c1.y);
        *(float4*)(ob + 32 + tx * 4) = make_float4(c2.x, c2.y, c3.x, c3.y);
    }
}

// ======================================================================
extern "C" void kernel_launch(void* const* d_in, const int* in_sizes, int n_in,
                              void* d_out, int out_size)
{
    const float* q     = (const float*)d_in[0];
    const float* k     = (const float*)d_in[1];
    const float* v     = (const float*)d_in[2];
    const float* sigma = (const float*)d_in[3];

    float* out    = (float*)d_out;
    float* Vout   = out;                                        // [B,L,H,E]
    float* series = Vout + (size_t)B_ * L_ * H_ * E_;           // [B,H,L,L]
    float* prior  = series + (size_t)BH_ * L_ * L_;             // [B,H,L,L]
    float* sigf   = prior + (size_t)BH_ * L_ * L_;              // [B,H,L,L]

    dim3 g1(4, 4, BH_);
    gemm_qk_kernel<<<g1, 256>>>(q, k, series);

    softmax_prior_kernel<<<(BH_ * L_) / 8, 256>>>(series, sigma, prior, sigf);

    dim3 g2(4, BH_);
    gemm_pv_kernel<<<g2, 128>>>(series, v, Vout);
}

// round 3
// speedup vs baseline: 1.0500x; 1.0500x over previous
#include <cuda_runtime.h>
#include <cstdint>

// Problem dims
#define B_ 16
#define L_ 512
#define H_ 8
#define E_ 64
#define BH_ (B_ * H_)          // 128
#define SCALE 0.125f           // 1/sqrt(64)

// ---------- f32x2 packed helpers ----------
__device__ __forceinline__ unsigned long long dup2(float a) {
    unsigned long long r;
    asm("mov.b64 %0, {%1, %1};" : "=l"(r) : "f"(a));
    return r;
}
__device__ __forceinline__ void fma2(unsigned long long& d,
                                     unsigned long long a,
                                     unsigned long long b) {
    asm("fma.rn.f32x2 %0, %1, %2, %0;" : "+l"(d) : "l"(a), "l"(b));
}
__device__ __forceinline__ float2 unpk(unsigned long long v) {
    float2 f;
    asm("mov.b64 {%0, %1}, %2;" : "=f"(f.x), "=f"(f.y) : "l"(v));
    return f;
}

// Accurate exp immune to fast-math flags: hi/lo split + ex2.approx.
__device__ __forceinline__ float exp_acc(float x) {
    float m = __fmul_rn(x, 1.4426950408889634f);
    float t = __fmaf_rn(x, 1.925962991e-8f, m);
    float r;
    asm("ex2.approx.ftz.f32 %0, %1;" : "=f"(r) : "f"(t));
    return r;
}

// ======================================================================
// Kernel 1: attn[bh, l, s] = SCALE * sum_e Q[b,l,h,e] * K[b,s,h,e]
// 128x128 tile per CTA, 256 threads, 2 CTAs/SM (reg-capped).
// ======================================================================
__global__ void __launch_bounds__(256, 2) gemm_qk_kernel(
    const float* __restrict__ q,
    const float* __restrict__ k,
    float* __restrict__ attn)
{
    __shared__ float AsT[32][132];   // [e within chunk][row i]
    __shared__ float BsT[32][132];

    const int bh = blockIdx.z;
    const int b  = bh >> 3;
    const int h  = bh & 7;
    const int it = blockIdx.y;
    const int jt = blockIdx.x;
    const int tid = threadIdx.x;
    const int tx = tid & 15;
    const int ty = tid >> 4;

    unsigned long long acc[8][4];
#pragma unroll
    for (int i = 0; i < 8; i++)
#pragma unroll
        for (int j = 0; j < 4; j++) acc[i][j] = 0ull;

    const float* qb = q + ((size_t)(b * L_) * H_ + h) * E_;
    const float* kb = k + ((size_t)(b * L_) * H_ + h) * E_;

#pragma unroll
    for (int ec = 0; ec < 2; ec++) {
#pragma unroll
        for (int r = 0; r < 4; r++) {
            int idx = tid + r * 256;
            int i   = idx >> 3;
            int e4  = idx & 7;
            int e   = ec * 32 + e4 * 4;
            float4 va = *(const float4*)(qb + (size_t)(it * 128 + i) * (H_ * E_) + e);
            AsT[e4 * 4 + 0][i] = va.x;
            AsT[e4 * 4 + 1][i] = va.y;
            AsT[e4 * 4 + 2][i] = va.z;
            AsT[e4 * 4 + 3][i] = va.w;
            float4 vb = *(const float4*)(kb + (size_t)(jt * 128 + i) * (H_ * E_) + e);
            BsT[e4 * 4 + 0][i] = vb.x;
            BsT[e4 * 4 + 1][i] = vb.y;
            BsT[e4 * 4 + 2][i] = vb.z;
            BsT[e4 * 4 + 3][i] = vb.w;
        }
        __syncthreads();

#pragma unroll
        for (int ee = 0; ee < 32; ee++) {
            float4 a0 = *(const float4*)&AsT[ee][ty * 4];
            float4 a1 = *(const float4*)&AsT[ee][64 + ty * 4];
            ulonglong2 b0 = *(const ulonglong2*)&BsT[ee][tx * 4];
            ulonglong2 b1 = *(const ulonglong2*)&BsT[ee][64 + tx * 4];

            unsigned long long ad[8];
            ad[0] = dup2(a0.x); ad[1] = dup2(a0.y);
            ad[2] = dup2(a0.z); ad[3] = dup2(a0.w);
            ad[4] = dup2(a1.x); ad[5] = dup2(a1.y);
            ad[6] = dup2(a1.z); ad[7] = dup2(a1.w);
            unsigned long long bp[4] = {b0.x, b0.y, b1.x, b1.y};

#pragma unroll
            for (int i = 0; i < 8; i++)
#pragma unroll
                for (int j = 0; j < 4; j++)
                    fma2(acc[i][j], ad[i], bp[j]);
        }
        __syncthreads();
    }

    float* outb = attn + ((size_t)bh * L_ + it * 128) * L_ + jt * 128;
#pragma unroll
    for (int ii = 0; ii < 8; ii++) {
        int row = (ii < 4) ? (ty * 4 + ii) : (64 + ty * 4 + ii - 4);
        float2 c0 = unpk(acc[ii][0]);
        float2 c1 = unpk(acc[ii][1]);
        float2 c2 = unpk(acc[ii][2]);
        float2 c3 = unpk(acc[ii][3]);
        float4 w0 = make_float4(c0.x * SCALE, c0.y * SCALE, c1.x * SCALE, c1.y * SCALE);
        float4 w1 = make_float4(c2.x * SCALE, c2.y * SCALE, c3.x * SCALE, c3.y * SCALE);
        *(float4*)(outb + (size_t)row * L_ + tx * 4) = w0;
        *(float4*)(outb + (size_t)row * L_ + 64 + tx * 4) = w1;
    }
}

// ======================================================================
// Kernel 2: per-row softmax (in-place) + prior + sigma_full.
// ======================================================================
__global__ void __launch_bounds__(256) softmax_prior_kernel(
    float* __restrict__ series,
    const float* __restrict__ sigma,
    float* __restrict__ prior,
    float* __restrict__ sigf)
{
    const int w    = threadIdx.x >> 5;
    const int lane = threadIdx.x & 31;
    const int r    = blockIdx.x * 8 + w;
    const int bh   = r >> 9;
    const int l    = r & 511;
    const int b    = bh >> 3;
    const int h    = bh & 7;

    float* row = series + (size_t)r * L_;
    float4 vv[4];
#pragma unroll
    for (int t = 0; t < 4; t++)
        vv[t] = *(const float4*)(row + t * 128 + lane * 4);

    float m = vv[0].x;
#pragma unroll
    for (int t = 0; t < 4; t++) {
        m = fmaxf(m, fmaxf(fmaxf(vv[t].x, vv[t].y), fmaxf(vv[t].z, vv[t].w)));
    }
#pragma unroll
    for (int o = 16; o > 0; o >>= 1)
        m = fmaxf(m, __shfl_xor_sync(0xffffffffu, m, o));

    float s = 0.f;
#pragma unroll
    for (int t = 0; t < 4; t++) {
        vv[t].x = exp_acc(vv[t].x - m); s += vv[t].x;
        vv[t].y = exp_acc(vv[t].y - m); s += vv[t].y;
        vv[t].z = exp_acc(vv[t].z - m); s += vv[t].z;
        vv[t].w = exp_acc(vv[t].w - m); s += vv[t].w;
    }
#pragma unroll
    for (int o = 16; o > 0; o >>= 1)
        s += __shfl_xor_sync(0xffffffffu, s, o);

    const float inv = __fdiv_rn(1.f, s);
#pragma unroll
    for (int t = 0; t < 4; t++) {
        vv[t].x *= inv; vv[t].y *= inv; vv[t].z *= inv; vv[t].w *= inv;
        *(float4*)(row + t * 128 + lane * 4) = vv[t];
    }

    // sigma -> bandwidth: 3^s correctly rounded in double; exact subtract.
    float sg;
    if (lane == 0) {
        double xd = (double)sigma[((size_t)b * L_ + l) * H_ + h];
        double sd = 1.0 / (1.0 + exp(-5.0 * xd));
        float sgm = (float)(sd + 1e-5);
        double P  = exp2((double)sgm * 1.5849625007211562);  // 3^sgm
        sg = (float)P - 1.0f;
    }
    sg = __shfl_sync(0xffffffffu, sg, 0);

    const float c    = __fdiv_rn(0.3989422804014327f, sg);
    const float sg2  = __fmul_rn(sg, sg);
    const float den  = __fmul_rn(2.0f, sg2);
    const float rinv = __fdiv_rn(1.0f, den);

    float* pr = prior + (size_t)r * L_;
    float* sf = sigf + (size_t)r * L_;
    const float4 sgv = make_float4(sg, sg, sg, sg);
#pragma unroll
    for (int t = 0; t < 4; t++) {
        int j0 = t * 128 + lane * 4;
        float d0 = (float)(l - j0);
        float d1 = (float)(l - (j0 + 1));
        float d2 = (float)(l - (j0 + 2));
        float d3 = (float)(l - (j0 + 3));
        float4 pv;
        pv.x = __fmul_rn(c, exp_acc(-__fmul_rn(__fmul_rn(d0, d0), rinv)));
        pv.y = __fmul_rn(c, exp_acc(-__fmul_rn(__fmul_rn(d1, d1), rinv)));
        pv.z = __fmul_rn(c, exp_acc(-__fmul_rn(__fmul_rn(d2, d2), rinv)));
        pv.w = __fmul_rn(c, exp_acc(-__fmul_rn(__fmul_rn(d3, d3), rinv)));
        *(float4*)(pr + j0) = pv;
        *(float4*)(sf + j0) = sgv;
    }
}

// ======================================================================
// Kernel 3: V[b,l,h,d] = sum_s P[bh,l,s] * values[b,s,h,d]
// 128x64 tile per CTA, 256 threads, 8M x 4N thread tile (32 acc regs).
// ======================================================================
__global__ void __launch_bounds__(256) gemm_pv_kernel(
    const float* __restrict__ p,
    const float* __restrict__ v,
    float* __restrict__ out)
{
    __shared__ float PsT[32][132];   // [s within chunk][row i]
    __shared__ float Vs[32][68];     // [s][d]

    const int bh = blockIdx.y;
    const int b  = bh >> 3;
    const int h  = bh & 7;
    const int mt = blockIdx.x;       // l-tile (0..3)
    const int tid = threadIdx.x;
    const int tx = tid & 15;         // 16 N-groups of 4 cols
    const int ty = tid >> 4;         // 16 M-groups of 8 rows

    unsigned long long acc[8][2];
#pragma unroll
    for (int i = 0; i < 8; i++) { acc[i][0] = 0ull; acc[i][1] = 0ull; }

    const float* prow = p + ((size_t)bh * L_ + mt * 128) * L_;
    const float* vb   = v + ((size_t)(b * L_) * H_ + h) * E_;

    for (int sc = 0; sc < 16; sc++) {
        // load P tile 128x32 transposed: 1024 float4 / 256 thr = 4 iters
#pragma unroll
        for (int r = 0; r < 4; r++) {
            int idx = tid + r * 256;
            int i   = idx >> 3;        // 0..127
            int s4  = idx & 7;         // 0..7
            float4 vp = *(const float4*)(prow + (size_t)i * L_ + sc * 32 + s4 * 4);
            PsT[s4 * 4 + 0][i] = vp.x;
            PsT[s4 * 4 + 1][i] = vp.y;
            PsT[s4 * 4 + 2][i] = vp.z;
            PsT[s4 * 4 + 3][i] = vp.w;
        }
        // load V tile 32x64: 512 float4 / 256 thr = 2 iters
#pragma unroll
        for (int r = 0; r < 2; r++) {
            int idx = tid + r * 256;
            int s   = idx >> 4;        // 0..31
            int e4  = idx & 15;        // 0..15
            *(float4*)&Vs[s][e4 * 4] =
                *(const float4*)(vb + (size_t)(sc * 32 + s) * (H_ * E_) + e4 * 4);
        }
        __syncthreads();

#pragma unroll
        for (int ss = 0; ss < 32; ss++) {
            float4 p0 = *(const float4*)&PsT[ss][ty * 4];
            float4 p1 = *(const float4*)&PsT[ss][64 + ty * 4];
            ulonglong2 v0 = *(const ulonglong2*)&Vs[ss][tx * 4];

            unsigned long long ad[8];
            ad[0] = dup2(p0.x); ad[1] = dup2(p0.y);
            ad[2] = dup2(p0.z); ad[3] = dup2(p0.w);
            ad[4] = dup2(p1.x); ad[5] = dup2(p1.y);
            ad[6] = dup2(p1.z); ad[7] = dup2(p1.w);

#pragma unroll
            for (int i = 0; i < 8; i++) {
                fma2(acc[i][0], ad[i], v0.x);
                fma2(acc[i][1], ad[i], v0.y);
            }
        }
        __syncthreads();
    }

    // epilogue: out[b,l,h,d]
#pragma unroll
    for (int ii = 0; ii < 8; ii++) {
        int row = (ii < 4) ? (ty * 4 + ii) : (64 + ty * 4 + ii - 4);
        int l = mt * 128 + row;
        float* ob = out + (((size_t)b * L_ + l) * H_ + h) * E_;
        float2 c0 = unpk(acc[ii][0]);
        float2 c1 = unpk(acc[ii][1]);
        *(float4*)(ob + tx * 4) = make_float4(c0.x, c0.y, c1.x, c1.y);
    }
}

// ======================================================================
extern "C" void kernel_launch(void* const* d_in, const int* in_sizes, int n_in,
                              void* d_out, int out_size)
{
    const float* q     = (const float*)d_in[0];
    const float* k     = (const float*)d_in[1];
    const float* v     = (const float*)d_in[2];
    const float* sigma = (const float*)d_in[3];

    float* out    = (float*)d_out;
    float* Vout   = out;                                        // [B,L,H,E]
    float* series = Vout + (size_t)B_ * L_ * H_ * E_;           // [B,H,L,L]
    float* prior  = series + (size_t)BH_ * L_ * L_;             // [B,H,L,L]
    float* sigf   = prior + (size_t)BH_ * L_ * L_;              // [B,H,L,L]

    dim3 g1(4, 4, BH_);
    gemm_qk_kernel<<<g1, 256>>>(q, k, series);

    softmax_prior_kernel<<<(BH_ * L_) / 8, 256>>>(series, sigma, prior, sigf);

    dim3 g2(4, BH_);
    gemm_pv_kernel<<<g2, 256>>>(series, v, Vout);
}

// round 5
// speedup vs baseline: 1.2340x; 1.1753x over previous
#include <cuda_runtime.h>
#include <cuda_bf16.h>
#include <cstdint>

// Problem dims
#define B_ 16
#define L_ 512
#define H_ 8
#define E_ 64
#define BH_ (B_ * H_)          // 128

// ===================== helpers =====================
__device__ __forceinline__ uint32_t smem_u32(const void* p) {
    uint32_t a;
    asm("{ .reg .u64 t; cvta.to.shared.u64 t, %1; cvt.u32.u64 %0, t; }"
        : "=r"(a) : "l"(p));
    return a;
}
// pack two floats -> bf16x2 (v0 -> low half / lower address, v1 -> high half)
__device__ __forceinline__ uint32_t bf16x2_of(float v0, float v1) {
    uint32_t r;
    asm("cvt.rn.bf16x2.f32 %0, %1, %2;" : "=r"(r) : "f"(v1), "f"(v0));
    return r;
}
__device__ __forceinline__ uint32_t lds32(uint32_t addr) {
    uint32_t v;
    asm volatile("ld.shared.b32 %0, [%1];" : "=r"(v) : "r"(addr));
    return v;
}
__device__ __forceinline__ void sts64(uint32_t addr, float c0, float c1) {
    asm volatile("st.shared.v2.f32 [%0], {%1,%2};" :: "r"(addr), "f"(c0), "f"(c1) : "memory");
}
// m16n8k16 row.col bf16 -> f32 acc
__device__ __forceinline__ void mma16816(float* c, const uint32_t* a, const uint32_t* b) {
    asm volatile(
        "mma.sync.aligned.m16n8k16.row.col.f32.bf16.bf16.f32 "
        "{%0,%1,%2,%3}, {%4,%5,%6,%7}, {%8,%9}, {%0,%1,%2,%3};"
        : "+f"(c[0]), "+f"(c[1]), "+f"(c[2]), "+f"(c[3])
        : "r"(a[0]), "r"(a[1]), "r"(a[2]), "r"(a[3]), "r"(b[0]), "r"(b[1]));
}
// Accurate exp immune to fast-math flags.
__device__ __forceinline__ float exp_acc(float x) {
    float m = __fmul_rn(x, 1.4426950408889634f);
    float t = __fmaf_rn(x, 1.925962991e-8f, m);
    float r;
    asm("ex2.approx.ftz.f32 %0, %1;" : "=f"(r) : "f"(t));
    return r;
}

// split one float4 into hi/lo bf16x2 pairs and store (8B each)
__device__ __forceinline__ void split_store4(char* smem, uint32_t offHi, uint32_t offLo, float4 v) {
    uint32_t h01 = bf16x2_of(v.x, v.y);
    uint32_t h23 = bf16x2_of(v.z, v.w);
    float l0 = v.x - __uint_as_float(h01 << 16);
    float l1 = v.y - __uint_as_float(h01 & 0xFFFF0000u);
    float l2 = v.z - __uint_as_float(h23 << 16);
    float l3 = v.w - __uint_as_float(h23 & 0xFFFF0000u);
    *(uint2*)(smem + offHi) = make_uint2(h01, h23);
    *(uint2*)(smem + offLo) = make_uint2(bf16x2_of(l0, l1), bf16x2_of(l2, l3));
}

// ======================================================================
// Kernel 1 (HMMA): scores[bh,l,s] = sum_e (Q/8)[l,e] K[s,e]
// CTA 128x128, K=64. bf16 3-product split. 256 thr, warp grid 2m x 4n.
// smem rows stride 72 bf16 (144B) -> conflict-free fragment LDS.
// ======================================================================
#define QK_ST 72
#define QK_QHI 0
#define QK_QLO 18432
#define QK_KHI 36864
#define QK_KLO 55296
#define QK_SMEM 73728          // also >= stage 128*132*4 = 67584

__global__ void __launch_bounds__(256, 2)
qk_mma_kernel(const float* __restrict__ q, const float* __restrict__ k,
              float* __restrict__ attn)
{
    extern __shared__ char smem[];
    const uint32_t sb = smem_u32(smem);
    const int tid = threadIdx.x;
    const int wid = tid >> 5;
    const int lane = tid & 31;

    const int bh = blockIdx.z;
    const int b  = bh >> 3;
    const int h  = bh & 7;
    const int it = blockIdx.y;
    const int jt = blockIdx.x;

    const float* qbase = q + (size_t)(b * L_ + it * 128) * (H_ * E_) + h * E_;
    const float* kbase = k + (size_t)(b * L_ + jt * 128) * (H_ * E_) + h * E_;

    // load + split: 128 rows x 64 cols each for Q (scaled) and K
#pragma unroll
    for (int i = tid; i < 2048; i += 256) {
        int row = i >> 4, e4 = i & 15;
        uint32_t off = (uint32_t)row * (QK_ST * 2) + e4 * 8;
        float4 va = *(const float4*)(qbase + (size_t)row * (H_ * E_) + e4 * 4);
        va.x *= 0.125f; va.y *= 0.125f; va.z *= 0.125f; va.w *= 0.125f;
        split_store4(smem, QK_QHI + off, QK_QLO + off, va);
        float4 vb = *(const float4*)(kbase + (size_t)row * (H_ * E_) + e4 * 4);
        split_store4(smem, QK_KHI + off, QK_KLO + off, vb);
    }
    __syncthreads();

    const int wm = wid & 1;        // 2 m-tiles of 64
    const int wn = wid >> 1;       // 4 n-tiles of 32
    const int r  = lane >> 2;
    const int kkB = (lane & 3) * 4;  // byte offset of k-pair

    float acc[4][4][4];
#pragma unroll
    for (int mb = 0; mb < 4; mb++)
#pragma unroll
        for (int nb = 0; nb < 4; nb++)
#pragma unroll
            for (int x = 0; x < 4; x++) acc[mb][nb][x] = 0.f;

    const uint32_t abase[3] = {sb + QK_QHI, sb + QK_QHI, sb + QK_QLO};
    const uint32_t bbase[3] = {sb + QK_KHI, sb + QK_KLO, sb + QK_KHI};

#pragma unroll
    for (int pr = 0; pr < 3; pr++) {
        uint32_t Ab = abase[pr], Bb = bbase[pr];
#pragma unroll
        for (int ks = 0; ks < 4; ks++) {
            uint32_t kByte = ks * 32 + kkB;   // ks*16 bf16 = 32B
            uint32_t a[4][4];
#pragma unroll
            for (int mb = 0; mb < 4; mb++) {
                uint32_t ad = Ab + (uint32_t)(wm * 64 + mb * 16 + r) * (QK_ST * 2) + kByte;
                a[mb][0] = lds32(ad);
                a[mb][1] = lds32(ad + 8 * QK_ST * 2);
                a[mb][2] = lds32(ad + 16);
                a[mb][3] = lds32(ad + 8 * QK_ST * 2 + 16);
            }
            uint32_t bf[4][2];
#pragma unroll
            for (int nb = 0; nb < 4; nb++) {
                uint32_t bd = Bb + (uint32_t)(wn * 32 + nb * 8 + r) * (QK_ST * 2) + kByte;
                bf[nb][0] = lds32(bd);
                bf[nb][1] = lds32(bd + 16);
            }
#pragma unroll
            for (int mb = 0; mb < 4; mb++)
#pragma unroll
                for (int nb = 0; nb < 4; nb++)
                    mma16816(acc[mb][nb], a[mb], bf[nb]);
        }
    }
    __syncthreads();   // done reading Q/K tiles; reuse smem as f32 stage

    // stage 128x128 f32, stride 132
#pragma unroll
    for (int mb = 0; mb < 4; mb++)
#pragma unroll
        for (int nb = 0; nb < 4; nb++) {
            uint32_t row = wm * 64 + mb * 16 + r;
            uint32_t col = wn * 32 + nb * 8 + (lane & 3) * 2;
            uint32_t ad = sb + (row * 132 + col) * 4;
            sts64(ad, acc[mb][nb][0], acc[mb][nb][1]);
            sts64(ad + 8 * 132 * 4, acc[mb][nb][2], acc[mb][nb][3]);
        }
    __syncthreads();

    float* outb = attn + ((size_t)bh * L_ + it * 128) * L_ + jt * 128;
#pragma unroll
    for (int i = tid; i < 4096; i += 256) {
        int row = i >> 5, c4 = i & 31;
        float4 vv = *(const float4*)(smem + (row * 132 + c4 * 4) * 4);
        *(float4*)(outb + (size_t)row * L_ + c4 * 4) = vv;
    }
}

// ======================================================================
// Kernel 2: per-row softmax (in-place) + prior + sigma_full. (unchanged)
// ======================================================================
__global__ void __launch_bounds__(256) softmax_prior_kernel(
    float* __restrict__ series,
    const float* __restrict__ sigma,
    float* __restrict__ prior,
    float* __restrict__ sigf)
{
    const int w    = threadIdx.x >> 5;
    const int lane = threadIdx.x & 31;
    const int r    = blockIdx.x * 8 + w;
    const int bh   = r >> 9;
    const int l    = r & 511;
    const int b    = bh >> 3;
    const int h    = bh & 7;

    float* row = series + (size_t)r * L_;
    float4 vv[4];
#pragma unroll
    for (int t = 0; t < 4; t++)
        vv[t] = *(const float4*)(row + t * 128 + lane * 4);

    float m = vv[0].x;
#pragma unroll
    for (int t = 0; t < 4; t++)
        m = fmaxf(m, fmaxf(fmaxf(vv[t].x, vv[t].y), fmaxf(vv[t].z, vv[t].w)));
#pragma unroll
    for (int o = 16; o > 0; o >>= 1)
        m = fmaxf(m, __shfl_xor_sync(0xffffffffu, m, o));

    float s = 0.f;
#pragma unroll
    for (int t = 0; t < 4; t++) {
        vv[t].x = exp_acc(vv[t].x - m); s += vv[t].x;
        vv[t].y = exp_acc(vv[t].y - m); s += vv[t].y;
        vv[t].z = exp_acc(vv[t].z - m); s += vv[t].z;
        vv[t].w = exp_acc(vv[t].w - m); s += vv[t].w;
    }
#pragma unroll
    for (int o = 16; o > 0; o >>= 1)
        s += __shfl_xor_sync(0xffffffffu, s, o);

    const float inv = __fdiv_rn(1.f, s);
#pragma unroll
    for (int t = 0; t < 4; t++) {
        vv[t].x *= inv; vv[t].y *= inv; vv[t].z *= inv; vv[t].w *= inv;
        *(float4*)(row + t * 128 + lane * 4) = vv[t];
    }

    float sg;
    if (lane == 0) {
        double xd = (double)sigma[((size_t)b * L_ + l) * H_ + h];
        double sd = 1.0 / (1.0 + exp(-5.0 * xd));
        float sgm = (float)(sd + 1e-5);
        double P  = exp2((double)sgm * 1.5849625007211562);  // 3^sgm
        sg = (float)P - 1.0f;
    }
    sg = __shfl_sync(0xffffffffu, sg, 0);

    const float c    = __fdiv_rn(0.3989422804014327f, sg);
    const float sg2  = __fmul_rn(sg, sg);
    const float den  = __fmul_rn(2.0f, sg2);
    const float rinv = __fdiv_rn(1.0f, den);

    float* pr = prior + (size_t)r * L_;
    float* sf = sigf + (size_t)r * L_;
    const float4 sgv = make_float4(sg, sg, sg, sg);
#pragma unroll
    for (int t = 0; t < 4; t++) {
        int j0 = t * 128 + lane * 4;
        float d0 = (float)(l - j0);
        float d1 = (float)(l - (j0 + 1));
        float d2 = (float)(l - (j0 + 2));
        float d3 = (float)(l - (j0 + 3));
        float4 pv;
        pv.x = __fmul_rn(c, exp_acc(-__fmul_rn(__fmul_rn(d0, d0), rinv)));
        pv.y = __fmul_rn(c, exp_acc(-__fmul_rn(__fmul_rn(d1, d1), rinv)));
        pv.z = __fmul_rn(c, exp_acc(-__fmul_rn(__fmul_rn(d2, d2), rinv)));
        pv.w = __fmul_rn(c, exp_acc(-__fmul_rn(__fmul_rn(d3, d3), rinv)));
        *(float4*)(pr + j0) = pv;
        *(float4*)(sf + j0) = sgv;
    }
}

// ======================================================================
// Kernel 3 (HMMA): V[b,l,h,d] = sum_s P[bh,l,s] * values[b,s,h,d]
// CTA 128x64, K=512 in 8 chunks of 64. V transposed in smem (K-major).
// 256 thr, warp grid 2m x 4n (warp tile 64x16).
// ======================================================================
#define PV_ST 72
#define PV_PHI 0
#define PV_PLO 18432
#define PV_VHI 36864           // 64 x 72 bf16
#define PV_VLO 46080
#define PV_SMEM 55296          // stage needs 128*68*4 = 34816, fits

__global__ void __launch_bounds__(256, 2)
pv_mma_kernel(const float* __restrict__ p, const float* __restrict__ v,
              float* __restrict__ out)
{
    extern __shared__ char smem[];
    const uint32_t sb = smem_u32(smem);
    const int tid = threadIdx.x;
    const int wid = tid >> 5;
    const int lane = tid & 31;

    const int bh = blockIdx.y;
    const int b  = bh >> 3;
    const int h  = bh & 7;
    const int mt = blockIdx.x;

    const float* prow  = p + ((size_t)bh * L_ + mt * 128) * L_;
    const float* vbase = v + (size_t)b * L_ * H_ * E_ + h * E_;

    const int wm = wid & 1;
    const int wn = wid >> 1;       // 4 n-tiles of 16
    const int r  = lane >> 2;
    const int kkB = (lane & 3) * 4;

    float acc[4][2][4];
#pragma unroll
    for (int mb = 0; mb < 4; mb++)
#pragma unroll
        for (int nb = 0; nb < 2; nb++)
#pragma unroll
            for (int x = 0; x < 4; x++) acc[mb][nb][x] = 0.f;

    const uint32_t abase[3] = {sb + PV_PHI, sb + PV_PHI, sb + PV_PLO};
    const uint32_t bbase[3] = {sb + PV_VHI, sb + PV_VLO, sb + PV_VHI};

    for (int c = 0; c < 8; c++) {
        // P chunk 128 x 64
#pragma unroll
        for (int i = tid; i < 2048; i += 256) {
            int row = i >> 4, s4 = i & 15;
            uint32_t off = (uint32_t)row * (PV_ST * 2) + s4 * 8;
            float4 va = *(const float4*)(prow + (size_t)row * L_ + c * 64 + s4 * 4);
            split_store4(smem, PV_PHI + off, PV_PLO + off, va);
        }
        // V chunk 64 s x 64 d, transposed -> Vt[d][s]
#pragma unroll
        for (int i = tid; i < 1024; i += 256) {
            int s = i >> 4, d4 = i & 15;
            float4 vv = *(const float4*)(vbase + (size_t)(c * 64 + s) * (H_ * E_) + d4 * 4);
            float xs[4] = {vv.x, vv.y, vv.z, vv.w};
#pragma unroll
            for (int j = 0; j < 4; j++) {
                __nv_bfloat16 hb = __float2bfloat16(xs[j]);
                float hf = __bfloat162float(hb);
                __nv_bfloat16 lb = __float2bfloat16(xs[j] - hf);
                uint32_t off = (uint32_t)(d4 * 4 + j) * (PV_ST * 2) + s * 2;
                *(__nv_bfloat16*)(smem + PV_VHI + off) = hb;
                *(__nv_bfloat16*)(smem + PV_VLO + off) = lb;
            }
        }
        __syncthreads();

#pragma unroll
        for (int pr = 0; pr < 3; pr++) {
            uint32_t Ab = abase[pr], Bb = bbase[pr];
#pragma unroll
            for (int ks = 0; ks < 4; ks++) {
                uint32_t kByte = ks * 32 + kkB;
                uint32_t a[4][4];
#pragma unroll
                for (int mb = 0; mb < 4; mb++) {
                    uint32_t ad = Ab + (uint32_t)(wm * 64 + mb * 16 + r) * (PV_ST * 2) + kByte;
                    a[mb][0] = lds32(ad);
                    a[mb][1] = lds32(ad + 8 * PV_ST * 2);
                    a[mb][2] = lds32(ad + 16);
                    a[mb][3] = lds32(ad + 8 * PV_ST * 2 + 16);
                }
                uint32_t bf[2][2];
#pragma unroll
                for (int nb = 0; nb < 2; nb++) {
                    uint32_t bd = Bb + (uint32_t)(wn * 16 + nb * 8 + r) * (PV_ST * 2) + kByte;
                    bf[nb][0] = lds32(bd);
                    bf[nb][1] = lds32(bd + 16);
                }
#pragma unroll
                for (int mb = 0; mb < 4; mb++)
#pragma unroll
                    for (int nb = 0; nb < 2; nb++)
                        mma16816(acc[mb][nb], a[mb], bf[nb]);
            }
        }
        __syncthreads();
    }

    // stage 128 x 64 f32, stride 68
#pragma unroll
    for (int mb = 0; mb < 4; mb++)
#pragma unroll
        for (int nb = 0; nb < 2; nb++) {
            uint32_t row = wm * 64 + mb * 16 + r;
            uint32_t col = wn * 16 + nb * 8 + (lane & 3) * 2;
            uint32_t ad = sb + (row * 68 + col) * 4;
            sts64(ad, acc[mb][nb][0], acc[mb][nb][1]);
            sts64(ad + 8 * 68 * 4, acc[mb][nb][2], acc[mb][nb][3]);
        }
    __syncthreads();

#pragma unroll
    for (int i = tid; i < 2048; i += 256) {
        int row = i >> 4, c4 = i & 15;
        int l = mt * 128 + row;
        float4 vv = *(const float4*)(smem + (row * 68 + c4 * 4) * 4);
        *(float4*)(out + (((size_t)b * L_ + l) * H_ + h) * E_ + c4 * 4) = vv;
    }
}

// ======================================================================
extern "C" void kernel_launch(void* const* d_in, const int* in_sizes, int n_in,
                              void* d_out, int out_size)
{
    const float* q     = (const float*)d_in[0];
    const float* k     = (const float*)d_in[1];
    const float* v     = (const float*)d_in[2];
    const float* sigma = (const float*)d_in[3];

    float* out    = (float*)d_out;
    float* Vout   = out;                                        // [B,L,H,E]
    float* series = Vout + (size_t)B_ * L_ * H_ * E_;           // [B,H,L,L]
    float* prior  = series + (size_t)BH_ * L_ * L_;             // [B,H,L,L]
    float* sigf   = prior + (size_t)BH_ * L_ * L_;              // [B,H,L,L]

    cudaFuncSetAttribute(qk_mma_kernel, cudaFuncAttributeMaxDynamicSharedMemorySize, QK_SMEM);
    cudaFuncSetAttribute(pv_mma_kernel, cudaFuncAttributeMaxDynamicSharedMemorySize, PV_SMEM);

    dim3 g1(4, 4, BH_);
    qk_mma_kernel<<<g1, 256, QK_SMEM>>>(q, k, series);

    softmax_prior_kernel<<<(BH_ * L_) / 8, 256>>>(series, sigma, prior, sigf);

    dim3 g2(4, BH_);
    pv_mma_kernel<<<g2, 256, PV_SMEM>>>(series, v, Vout);
}